// round 6
// baseline (speedup 1.0000x reference)
#include <cuda_runtime.h>
#include <math.h>

// Model dims
// B=64, T=512, F=161, V=32, L=64, H=128, E=32
// conv1: (64,1,512,161) -> (64,32,241,80), w (32,1,32,2), stride 2
// conv2: (64,32,241,80) -> (64,32,105,36), w (32,32,32,9), stride 2
// reshape -> (64,105,1152); enc GRU H=128, 105 steps
// decoder: 63 steps, attention over 105 enc states, fc -> (64,63,32)

#define NB 64
#define C1H 241
#define C1W 80
#define C2H 105
#define C2W 36

typedef unsigned long long ull;

// ---------------- device scratch (no allocations allowed) ----------------
__device__ float g_conv1[NB * 32 * C1H * C1W];
__device__ float g_conv2[NB * C2H * 1152];       // (b, t, c*36+w)
__device__ float g_xp   [NB * C2H * 384];
__device__ float g_eh   [NB * C2H * 128];
__device__ float g_embA [NB * 63 * 32];
__device__ float g_ip   [NB * 63 * 384];
__device__ float g_ctxs [NB * 63 * 128];
__device__ float g_wT   [128 * 384];             // dec_w_hh transposed (k-major)
// conv2 weights, per kh (9216 floats):
//   [0,8192): pairs  [ci][p=0..3][copair=0..15][4] = (w2p_co, w2p1_co, w2p_co1, w2p1_co1)
//   [8192,9216): kw=8 [ci][co]
__device__ float g_w2   [32 * 9216];

// ---------------- f32x2 packed helpers (Blackwell FFMA2 path) ----------------
__device__ __forceinline__ ull pk2(float lo, float hi) {
    ull r;
    asm("mov.b64 %0, {%1, %2};" : "=l"(r) : "f"(lo), "f"(hi));
    return r;
}
__device__ __forceinline__ void fma2(ull& d, ull a, ull b) {
    asm("fma.rn.f32x2 %0, %1, %2, %0;" : "+l"(d) : "l"(a), "l"(b));
}
__device__ __forceinline__ void upk2(ull v, float& lo, float& hi) {
    asm("mov.b64 {%0, %1}, %2;" : "=f"(lo), "=f"(hi) : "l"(v));
}

// ---------------- conv1: normalize + conv + relu ----------------
__global__ void conv1_kernel(const float* __restrict__ x,
                             const float* __restrict__ mean,
                             const float* __restrict__ stdv,
                             const float* __restrict__ w,
                             const float* __restrict__ bias) {
    int oh = blockIdx.x, b = blockIdx.y;
    __shared__ float s_x[32 * 161];
    __shared__ float s_w[2048];
    __shared__ float s_m[161], s_i[161];
    int tid = threadIdx.x;
    for (int i = tid; i < 161; i += 256) {
        s_m[i] = mean[i];
        s_i[i] = 1.0f / stdv[i];
    }
    for (int i = tid; i < 2048; i += 256) s_w[i] = w[i];
    __syncthreads();
    for (int i = tid; i < 32 * 161; i += 256) {
        int kh = i / 161, iw = i % 161;
        int ih = 2 * oh + kh;
        s_x[i] = (x[(b * 512 + ih) * 161 + iw] - s_m[iw]) * s_i[iw];
    }
    __syncthreads();

    int c = tid >> 3, owb = tid & 7;
    float acc[10];
#pragma unroll
    for (int j = 0; j < 10; j++) acc[j] = 0.f;
    for (int kh = 0; kh < 32; kh++) {
        float w0 = s_w[c * 64 + kh * 2], w1 = s_w[c * 64 + kh * 2 + 1];
        const float* xr = &s_x[kh * 161];
#pragma unroll
        for (int j = 0; j < 10; j++) {
            int ow = owb + 8 * j;
            acc[j] += w0 * xr[2 * ow] + w1 * xr[2 * ow + 1];
        }
    }
    float bb = bias[c];
#pragma unroll
    for (int j = 0; j < 10; j++) {
        int ow = owb + 8 * j;
        float v = acc[j] + bb;
        g_conv1[((size_t)(b * 32 + c) * C1H + oh) * C1W + ow] = v > 0.f ? v : 0.f;
    }
}

// -------- weight reorder for conv2: [co][ci][kh][kw] -> packed per-kh layout ----
__global__ void reorder_w2(const float* __restrict__ w) {
    int i = blockIdx.x * 256 + threadIdx.x;
    if (i >= 294912) return;
    int kw = i % 9; int t = i / 9;
    int kh = t & 31; t >>= 5;
    int ci = t & 31; int co = t >> 5;
    float v = w[i];
    int dst;
    if (kw < 8) {
        int p = kw >> 1, h = kw & 1;
        dst = kh * 9216 + (ci * 4 + p) * 64 + (co >> 1) * 4 + (co & 1) * 2 + h;
    } else {
        dst = kh * 9216 + 8192 + ci * 32 + co;
    }
    g_w2[dst] = v;
}

// ---------------- conv2 + relu + reshape, packed f32x2, 2 c_out/thread -------
// grid (53, 64), 192 threads. Block = (b, oh0..oh0+1); 96 thr per row:
// thread = (copair c2 = ltid&15, ow group g = ltid>>4). Each thread: co=2c2,2c2+1,
// ow = 6g..6g+5. Per ci: 10 x LDS.64 + 4 w LDS.128 + 1 w LDS.64, 54 fma2.
__global__ void conv2_kernel(const float* __restrict__ bias) {
    extern __shared__ __align__(16) float sm2[];
    float* s_in = sm2;            // 2 x 2560
    float* s_w  = sm2 + 5120;     // 9216
    int oh0 = blockIdx.x * 2, b = blockIdx.y;
    int tid = threadIdx.x;        // 192
    int sub = (tid >= 96) ? 1 : 0;
    int ltid = tid - sub * 96;
    int c2 = ltid & 15;
    int g = ltid >> 4;            // 0..5
    int oh = oh0 + sub;
    bool valid = (oh < C2H);

    ull acc2[2][6];
    ull acc8[6];
#pragma unroll
    for (int j = 0; j < 6; j++) {
        acc2[0][j] = 0ULL; acc2[1][j] = 0ULL; acc8[j] = 0ULL;
    }

    for (int kh = 0; kh < 32; kh++) {
        int ih0 = 2 * oh0 + kh;
        for (int i = tid; i < 5120; i += 192) {
            int r = i / 2560, j = i - r * 2560;
            int ci = j / 80, iw = j - ci * 80;
            int row = ih0 + 2 * r;
            s_in[i] = (row < C1H)
                ? g_conv1[((size_t)(b * 32 + ci) * C1H + row) * C1W + iw] : 0.f;
        }
        {
            const float4* src = (const float4*)&g_w2[kh * 9216];
            float4* dst = (float4*)s_w;
            for (int i = tid; i < 2304; i += 192) dst[i] = src[i];
        }
        __syncthreads();

#pragma unroll 1
        for (int ci = 0; ci < 32; ci++) {
            const ull* x64 = (const ull*)&s_in[sub * 2560 + ci * 80 + 12 * g];
            ull xb[10];
#pragma unroll
            for (int q = 0; q < 10; q++) xb[q] = x64[q];

            const float4* w4 = (const float4*)&s_w[ci * 256];
            float4 p0 = w4[c2];
            float4 p1 = w4[16 + c2];
            float4 p2 = w4[32 + c2];
            float4 p3 = w4[48 + c2];
            ull w8p = ((const ull*)&s_w[8192 + ci * 32])[c2];
            ull wa0 = pk2(p0.x, p0.y), wb0 = pk2(p0.z, p0.w);
            ull wa1 = pk2(p1.x, p1.y), wb1 = pk2(p1.z, p1.w);
            ull wa2 = pk2(p2.x, p2.y), wb2 = pk2(p2.z, p2.w);
            ull wa3 = pk2(p3.x, p3.y), wb3 = pk2(p3.z, p3.w);

#pragma unroll
            for (int j = 0; j < 6; j++) {
                fma2(acc2[0][j], wa0, xb[j]);
                fma2(acc2[1][j], wb0, xb[j]);
                fma2(acc2[0][j], wa1, xb[j + 1]);
                fma2(acc2[1][j], wb1, xb[j + 1]);
                fma2(acc2[0][j], wa2, xb[j + 2]);
                fma2(acc2[1][j], wb2, xb[j + 2]);
                fma2(acc2[0][j], wa3, xb[j + 3]);
                fma2(acc2[1][j], wb3, xb[j + 3]);
                float2 xt = *(float2*)&xb[j + 4];     // lo = xr[2j+8]
                fma2(acc8[j], w8p, pk2(xt.x, xt.x));
            }
        }
        __syncthreads();
    }
    if (valid) {
        int co = c2 * 2;
#pragma unroll
        for (int h = 0; h < 2; h++) {
            float bb = bias[co + h];
            float* dst = &g_conv2[((size_t)b * C2H + oh) * 1152 + (co + h) * 36 + 6 * g];
#pragma unroll
            for (int j = 0; j < 6; j++) {
                float lo, hi, l8, h8;
                upk2(acc2[h][j], lo, hi);
                upk2(acc8[j], l8, h8);
                float v = lo + hi + (h == 0 ? l8 : h8) + bb;
                dst[j] = v > 0.f ? v : 0.f;
            }
        }
    }
}

// ---------------- generic C[M,N] = A[M,K] * B[N,K]^T + bias ----------------
__global__ void gemm_nt(const float* __restrict__ A, const float* __restrict__ Bm,
                        const float* __restrict__ bias, float* __restrict__ C,
                        int M, int N, int K) {
    __shared__ float sA[8][128];
    __shared__ float sB[8][128];
    int bm = blockIdx.y * 128, bn = blockIdx.x * 128;
    int tid = threadIdx.x;
    int ty = tid >> 4, tx = tid & 15;
    float acc[8][8];
#pragma unroll
    for (int i = 0; i < 8; i++)
#pragma unroll
        for (int j = 0; j < 8; j++) acc[i][j] = 0.f;

    int lrow = tid >> 1, lk = (tid & 1) * 4;
    for (int k0 = 0; k0 < K; k0 += 8) {
        float4 av = make_float4(0.f, 0.f, 0.f, 0.f);
        float4 bv = make_float4(0.f, 0.f, 0.f, 0.f);
        if (bm + lrow < M) av = *(const float4*)&A[(size_t)(bm + lrow) * K + k0 + lk];
        if (bn + lrow < N) bv = *(const float4*)&Bm[(size_t)(bn + lrow) * K + k0 + lk];
        sA[lk + 0][lrow] = av.x; sA[lk + 1][lrow] = av.y;
        sA[lk + 2][lrow] = av.z; sA[lk + 3][lrow] = av.w;
        sB[lk + 0][lrow] = bv.x; sB[lk + 1][lrow] = bv.y;
        sB[lk + 2][lrow] = bv.z; sB[lk + 3][lrow] = bv.w;
        __syncthreads();
#pragma unroll
        for (int k = 0; k < 8; k++) {
            float a[8], bb[8];
            *(float4*)&a[0] = *(const float4*)&sA[k][ty * 8];
            *(float4*)&a[4] = *(const float4*)&sA[k][ty * 8 + 4];
            *(float4*)&bb[0] = *(const float4*)&sB[k][tx * 8];
            *(float4*)&bb[4] = *(const float4*)&sB[k][tx * 8 + 4];
#pragma unroll
            for (int i = 0; i < 8; i++)
#pragma unroll
                for (int j = 0; j < 8; j++) acc[i][j] += a[i] * bb[j];
        }
        __syncthreads();
    }
    for (int i = 0; i < 8; i++) {
        int m = bm + ty * 8 + i;
        if (m >= M) break;
        for (int j = 0; j < 8; j++) {
            int n = bn + tx * 8 + j;
            if (n < N) C[(size_t)m * N + n] = acc[i][j] + bias[n];
        }
    }
}

// ---------------- encoder GRU: one block per batch element ----------------
__global__ void encoder_kernel(const float* __restrict__ w_hh,
                               const float* __restrict__ b_hh) {
    extern __shared__ float sm[];
    float* s_w = sm;              // 384*132 = 50688 (padded stride)
    float* s_h = sm + 50688;      // 128
    float* s_gh = sm + 50816;     // 384
    int b = blockIdx.x, tid = threadIdx.x;
    for (int i = tid; i < 49152; i += 384) {
        int r = i >> 7, c = i & 127;
        s_w[r * 132 + c] = w_hh[i];
    }
    if (tid < 128) s_h[tid] = 0.f;
    __syncthreads();
    float bn = b_hh[tid];
    const float4* wr = (const float4*)&s_w[tid * 132];
    for (int t = 0; t < 105; t++) {
        float a0 = bn, a1 = 0.f;
#pragma unroll
        for (int k = 0; k < 16; k++) {
            float4 wv = wr[2 * k];
            float4 hv = ((const float4*)s_h)[2 * k];
            a0 += wv.x * hv.x + wv.y * hv.y + wv.z * hv.z + wv.w * hv.w;
            float4 wv2 = wr[2 * k + 1];
            float4 hv2 = ((const float4*)s_h)[2 * k + 1];
            a1 += wv2.x * hv2.x + wv2.y * hv2.y + wv2.z * hv2.z + wv2.w * hv2.w;
        }
        s_gh[tid] = a0 + a1;
        __syncthreads();
        if (tid < 128) {
            const float* xrow = &g_xp[((size_t)b * 105 + t) * 384];
            float r = 1.f / (1.f + __expf(-(xrow[tid] + s_gh[tid])));
            float z = 1.f / (1.f + __expf(-(xrow[128 + tid] + s_gh[128 + tid])));
            float nn = tanhf(xrow[256 + tid] + r * s_gh[256 + tid]);
            float hnew = (1.f - z) * nn + z * s_h[tid];
            s_h[tid] = hnew;
            g_eh[((size_t)b * 105 + t) * 128 + tid] = hnew;
        }
        __syncthreads();
    }
}

// ---------------- decoder: GRU step + attention, one block per batch ----------------
__device__ __forceinline__ float warpred_max(float v) {
#pragma unroll
    for (int o = 16; o; o >>= 1) v = fmaxf(v, __shfl_xor_sync(0xffffffffu, v, o));
    return v;
}
__device__ __forceinline__ float warpred_sum(float v) {
#pragma unroll
    for (int o = 16; o; o >>= 1) v += __shfl_xor_sync(0xffffffffu, v, o);
    return v;
}

__global__ void decoder_kernel(const float* __restrict__ b_hh) {
    extern __shared__ float sm[];
    float* s_eh = sm;              // 105*132 = 13860
    float* s_h = sm + 13860;       // 128 (carry = ctx)
    float* s_gh = sm + 13988;      // 384
    float* s_hx2 = sm + 14372;     // 128
    float* s_att = sm + 14500;     // 128
    float* s_red = sm + 14628;     // 32
    int b = blockIdx.x, tid = threadIdx.x;

    for (int i = tid; i < 13440; i += 384) {
        int t = i >> 7, k = i & 127;
        s_eh[t * 132 + k] = g_eh[(size_t)b * 105 * 128 + i];
    }
    if (tid < 128) s_h[tid] = 0.f;
    __syncthreads();

    float bn = b_hh[tid];
    for (int l = 0; l < 63; l++) {
        float a0 = bn, a1 = 0.f;
#pragma unroll 8
        for (int k = 0; k < 64; k++) {
            a0 += g_wT[k * 384 + tid] * s_h[k];
            a1 += g_wT[(k + 64) * 384 + tid] * s_h[k + 64];
        }
        s_gh[tid] = a0 + a1;
        __syncthreads();

        if (tid < 128) {
            const float* irow = &g_ip[((size_t)b * 63 + l) * 384];
            float r = 1.f / (1.f + __expf(-(irow[tid] + s_gh[tid])));
            float z = 1.f / (1.f + __expf(-(irow[128 + tid] + s_gh[128 + tid])));
            float nn = tanhf(irow[256 + tid] + r * s_gh[256 + tid]);
            s_hx2[tid] = (1.f - z) * nn + z * s_h[tid];
        }
        __syncthreads();

        float sc = -1e30f;
        if (tid < 105) {
            const float4* er = (const float4*)&s_eh[tid * 132];
            const float4* hx = (const float4*)s_hx2;
            float d = 0.f;
#pragma unroll 8
            for (int k = 0; k < 32; k++) {
                float4 e4 = er[k], h4 = hx[k];
                d += e4.x * h4.x + e4.y * h4.y + e4.z * h4.z + e4.w * h4.w;
            }
            sc = d;
        }
        float m = warpred_max(sc);
        if ((tid & 31) == 0) s_red[tid >> 5] = m;
        __syncthreads();
        if (tid < 32) {
            float wv = (tid < 12) ? s_red[tid] : -1e30f;
            wv = warpred_max(wv);
            if (tid == 0) s_red[12] = wv;
        }
        __syncthreads();
        float mx = s_red[12];
        float e = (tid < 105) ? __expf(sc - mx) : 0.f;
        float sv = warpred_sum(e);
        if ((tid & 31) == 0) s_red[16 + (tid >> 5)] = sv;
        if (tid < 128) s_att[tid] = e;
        __syncthreads();
        if (tid < 32) {
            float wv = (tid < 12) ? s_red[16 + tid] : 0.f;
            wv = warpred_sum(wv);
            if (tid == 0) s_red[13] = wv;
        }
        __syncthreads();
        float inv = 1.f / s_red[13];

        if (tid < 128) {
            float c = 0.f;
            for (int t = 0; t < 105; t++) c += s_att[t] * s_eh[t * 132 + tid];
            c *= inv;
            s_h[tid] = c;
            g_ctxs[((size_t)b * 63 + l) * 128 + tid] = c;
        }
        __syncthreads();
    }
}

// ---------------- small helpers ----------------
__global__ void emb_gather(const int* __restrict__ y, const float* __restrict__ emb) {
    int i = blockIdx.x * 256 + threadIdx.x;
    if (i >= NB * 63 * 32) return;
    int m = i >> 5, e = i & 31;
    int bb = m / 63, l = m % 63;
    int idx = y[bb * 64 + l];
    g_embA[i] = emb[idx * 32 + e];
}

__global__ void transpose_whh(const float* __restrict__ w) {
    int i = blockIdx.x * 256 + threadIdx.x;
    if (i < 49152) {
        int n = i >> 7, k = i & 127;
        g_wT[k * 384 + n] = w[i];
    }
}

// ---------------- launch ----------------
extern "C" void kernel_launch(void* const* d_in, const int* in_sizes, int n_in,
                              void* d_out, int out_size) {
    const float* x    = (const float*)d_in[0];
    const int*   y    = (const int*)d_in[1];
    const float* mean = (const float*)d_in[2];
    const float* stdv = (const float*)d_in[3];
    const float* c1w  = (const float*)d_in[4];
    const float* c1b  = (const float*)d_in[5];
    const float* c2w  = (const float*)d_in[6];
    const float* c2b  = (const float*)d_in[7];
    const float* gwih = (const float*)d_in[8];
    const float* gwhh = (const float*)d_in[9];
    const float* gbih = (const float*)d_in[10];
    const float* gbhh = (const float*)d_in[11];
    const float* emb  = (const float*)d_in[12];
    const float* dwih = (const float*)d_in[13];
    const float* dwhh = (const float*)d_in[14];
    const float* dbih = (const float*)d_in[15];
    const float* dbhh = (const float*)d_in[16];
    const float* fcw  = (const float*)d_in[17];
    const float* fcb  = (const float*)d_in[18];
    float* out = (float*)d_out;

    cudaFuncSetAttribute(encoder_kernel, cudaFuncAttributeMaxDynamicSharedMemorySize, 204800);
    cudaFuncSetAttribute(decoder_kernel, cudaFuncAttributeMaxDynamicSharedMemorySize, 58640);
    cudaFuncSetAttribute(conv2_kernel, cudaFuncAttributeMaxDynamicSharedMemorySize, 57400);

    void *p_conv2, *p_xp, *p_embA, *p_ip, *p_ctxs;
    cudaGetSymbolAddress(&p_conv2, g_conv2);
    cudaGetSymbolAddress(&p_xp, g_xp);
    cudaGetSymbolAddress(&p_embA, g_embA);
    cudaGetSymbolAddress(&p_ip, g_ip);
    cudaGetSymbolAddress(&p_ctxs, g_ctxs);

    reorder_w2<<<(294912 + 255) / 256, 256>>>(c2w);
    transpose_whh<<<192, 256>>>(dwhh);
    conv1_kernel<<<dim3(C1H, NB), 256>>>(x, mean, stdv, c1w, c1b);
    conv2_kernel<<<dim3(53, NB), 192, 57400>>>(c2b);
    // xp = conv_out @ gru_w_ih^T + gru_b_ih : (6720,1152)x(384,1152)
    gemm_nt<<<dim3(3, 53), 256>>>((const float*)p_conv2, gwih, gbih, (float*)p_xp,
                                  NB * C2H, 384, 1152);
    encoder_kernel<<<NB, 384, 204800>>>(gwhh, gbhh);

    emb_gather<<<(NB * 63 * 32 + 255) / 256, 256>>>(y, emb);
    // ip = emb_in @ dec_w_ih^T + dec_b_ih : (4032,32)x(384,32)
    gemm_nt<<<dim3(3, 32), 256>>>((const float*)p_embA, dwih, dbih, (float*)p_ip,
                                  NB * 63, 384, 32);
    decoder_kernel<<<NB, 384, 58640>>>(dbhh);
    // out = ctxs @ fc_w^T + fc_b : (4032,128)x(32,128)
    gemm_nt<<<dim3(1, 32), 256>>>((const float*)p_ctxs, fcw, fcb, out,
                                  NB * 63, 32, 128);
}